// round 1
// baseline (speedup 1.0000x reference)
#include <cuda_runtime.h>

// QuantileLoss: mean over [N,5] loss matrix built from preds[N,5], target[N,3].
// HBM-bound reduction: 128 MB read -> 1 float out.

__global__ void zero_out_kernel(float* out) {
    if (threadIdx.x == 0) out[0] = 0.0f;
}

__device__ __forceinline__ float row_loss(
    float p0, float p1, float p2, float p3, float p4,
    float t0, float t1, float t2)
{
    float d0 = p0 - t0;
    float d1 = p1 - t1;
    float d2 = p2 - t2;
    float main_mse = d0 * d0 + d1 * d1 + d2 * d2;

    float pen = (p4 - t2) * 4.0f;

    // lower
    float lo_th = t2 * 0.95f;
    float lo_d  = p3 - lo_th;
    float lower = (p3 > p2) ? pen : ((p3 > lo_th) ? 0.0f : lo_d * lo_d);

    // upper
    float up_th = t2 * 1.05f;
    float up_d  = p4 - up_th;
    float upper = (p4 < p2) ? pen : ((p4 < up_th) ? 0.0f : up_d * up_d);

    return main_mse + lower + upper;
}

__global__ void __launch_bounds__(256)
quantile_loss_kernel(const float4* __restrict__ preds4,
                     const float4* __restrict__ tgt4,
                     const float*  __restrict__ preds,
                     const float*  __restrict__ target,
                     float* __restrict__ out,
                     int nquads, int n_rows, float inv_count)
{
    int t = blockIdx.x * blockDim.x + threadIdx.x;
    float s = 0.0f;

    if (t < nquads) {
        // 4 rows = 20 preds floats = 5x float4 (aligned: 80*t bytes)
        float4 p0 = preds4[t * 5 + 0];
        float4 p1 = preds4[t * 5 + 1];
        float4 p2 = preds4[t * 5 + 2];
        float4 p3 = preds4[t * 5 + 3];
        float4 p4 = preds4[t * 5 + 4];
        // 4 rows = 12 target floats = 3x float4 (aligned: 48*t bytes)
        float4 g0 = tgt4[t * 3 + 0];
        float4 g1 = tgt4[t * 3 + 1];
        float4 g2 = tgt4[t * 3 + 2];

        // row 0: preds {p0.x p0.y p0.z p0.w p1.x}, tgt {g0.x g0.y g0.z}
        s += row_loss(p0.x, p0.y, p0.z, p0.w, p1.x, g0.x, g0.y, g0.z);
        // row 1: preds {p1.y p1.z p1.w p2.x p2.y}, tgt {g0.w g1.x g1.y}
        s += row_loss(p1.y, p1.z, p1.w, p2.x, p2.y, g0.w, g1.x, g1.y);
        // row 2: preds {p2.z p2.w p3.x p3.y p3.z}, tgt {g1.z g1.w g2.x}
        s += row_loss(p2.z, p2.w, p3.x, p3.y, p3.z, g1.z, g1.w, g2.x);
        // row 3: preds {p3.w p4.x p4.y p4.z p4.w}, tgt {g2.y g2.z g2.w}
        s += row_loss(p3.w, p4.x, p4.y, p4.z, p4.w, g2.y, g2.z, g2.w);
    }

    // tail rows (n_rows not divisible by 4) handled by thread 0 of block 0
    if (blockIdx.x == 0 && threadIdx.x == 0) {
        for (int r = nquads * 4; r < n_rows; r++) {
            s += row_loss(preds[r * 5 + 0], preds[r * 5 + 1], preds[r * 5 + 2],
                          preds[r * 5 + 3], preds[r * 5 + 4],
                          target[r * 3 + 0], target[r * 3 + 1], target[r * 3 + 2]);
        }
    }

    // warp reduce
    #pragma unroll
    for (int off = 16; off > 0; off >>= 1)
        s += __shfl_down_sync(0xFFFFFFFFu, s, off);

    __shared__ float warp_sums[8];
    int lane = threadIdx.x & 31;
    int wid  = threadIdx.x >> 5;
    if (lane == 0) warp_sums[wid] = s;
    __syncthreads();

    if (wid == 0) {
        s = (lane < (blockDim.x >> 5)) ? warp_sums[lane] : 0.0f;
        #pragma unroll
        for (int off = 4; off > 0; off >>= 1)
            s += __shfl_down_sync(0xFFFFFFFFu, s, off);
        if (lane == 0)
            atomicAdd(out, s * inv_count);
    }
}

extern "C" void kernel_launch(void* const* d_in, const int* in_sizes, int n_in,
                              void* d_out, int out_size)
{
    const float* preds  = (const float*)d_in[0];
    const float* target = (const float*)d_in[1];
    float* out = (float*)d_out;

    int n_rows = in_sizes[0] / 5;
    int nquads = n_rows / 4;
    float inv_count = 1.0f / (5.0f * (float)n_rows);

    zero_out_kernel<<<1, 32>>>(out);

    int threads = 256;
    int blocks = (nquads + threads - 1) / threads;
    if (blocks < 1) blocks = 1;
    quantile_loss_kernel<<<blocks, threads>>>(
        (const float4*)preds, (const float4*)target,
        preds, target, out, nquads, n_rows, inv_count);
}